// round 14
// baseline (speedup 1.0000x reference)
#include <cuda_runtime.h>
#include <cstdint>

typedef unsigned long long ull;

#define SEQ    512
#define BATCH  128
#define INPUT  128
#define HIDDEN 512
#define THREADS 512

// ---- recurrent smem layout (bytes) ----
// W slice  [512 k][64 n] fp32                          131072
// HS dup-staged h: [e 2][kq 8][k 64][bg 2][b 2] ull     32768 (2KB/chunk)
// scr partials: [e 2][kq 8][b 4][n 64] fp32             16384
#define HS_OFF   131072
#define SCR_OFF  163840
#define SMEM_BYTES 180224

// ---- global exchange state (no allocations allowed) ----
__device__ float    g_h[2][BATCH * HIDDEN];        // relu(h), parity buffered
__device__ unsigned g_flags[16][2][8 * 32];        // [group][engine][src*32] 128B-spaced

// ---------------------------------------------------------------------------
// init: zero g_h[0] (h0 = 0) and all flags (every launch -> deterministic)
// ---------------------------------------------------------------------------
__global__ void init_kernel()
{
    int i = blockIdx.x * blockDim.x + threadIdx.x;
    if (i < BATCH * HIDDEN) g_h[0][i] = 0.0f;
    if (i < 16 * 2 * 8 * 32) ((unsigned*)g_flags)[i] = 0u;
}

// ---------------------------------------------------------------------------
// Phase 1: proj[row,n] = sum_k input[row,k] * W_in[n,k] -> d_out
// ---------------------------------------------------------------------------
__global__ __launch_bounds__(256) void proj_kernel(
    const float* __restrict__ A, const float* __restrict__ W,
    float* __restrict__ C)
{
    __shared__ float As[64][65];
    __shared__ float Bs[64][65];
    const int tid = threadIdx.x, tx = tid & 15, ty = tid >> 4;
    const int row0 = blockIdx.x * 64, n0 = blockIdx.y * 64;
    float acc[4][4] = {};
    for (int k0 = 0; k0 < INPUT; k0 += 64) {
        #pragma unroll
        for (int i = 0; i < 16; i++) {
            int e = tid + i * 256, r = e >> 6, kk = e & 63;
            As[kk][r] = A[(row0 + r) * INPUT + k0 + kk];
            Bs[kk][r] = W[(n0 + r) * INPUT + k0 + kk];
        }
        __syncthreads();
        #pragma unroll 8
        for (int k = 0; k < 64; k++) {
            float a[4], b[4];
            #pragma unroll
            for (int i = 0; i < 4; i++) a[i] = As[k][ty * 4 + i];
            #pragma unroll
            for (int j = 0; j < 4; j++) b[j] = Bs[k][tx * 4 + j];
            #pragma unroll
            for (int i = 0; i < 4; i++)
                #pragma unroll
                for (int j = 0; j < 4; j++) acc[i][j] += a[i] * b[j];
        }
        __syncthreads();
    }
    #pragma unroll
    for (int i = 0; i < 4; i++) {
        int row = row0 + ty * 4 + i;
        #pragma unroll
        for (int j = 0; j < 4; j++)
            C[row * HIDDEN + n0 + tx * 4 + j] = acc[i][j];
    }
}

// ---- helpers ---------------------------------------------------------------
__device__ __forceinline__ void fma2(ull& d, ull a, ull b) {
    asm("fma.rn.f32x2 %0, %1, %2, %0;" : "+l"(d) : "l"(a), "l"(b));
}
__device__ __forceinline__ ull pk(float lo, float hi) {
    ull d; asm("mov.b64 %0, {%1, %2};" : "=l"(d) : "f"(lo), "f"(hi)); return d;
}
__device__ __forceinline__ uint32_t s2u(const void* p) {
    uint32_t a;
    asm("{ .reg .u64 t; cvta.to.shared.u64 t, %1; cvt.u32.u64 %0, t; }" : "=r"(a) : "l"(p));
    return a;
}

// ---------------------------------------------------------------------------
// Phase 2: persistent recurrence, no clusters. 128 CTAs (all resident):
//   group g = blockIdx/8 owns batch rows [8g,8g+8); rank = blockIdx%8 owns
//   hidden cols [64r,64r+64). Two engines (4 rows each), ANTI-PHASE seeded.
//   Exchange via L2 (monotonic flags, per-source chunk waits). Staging
//   duplicates each h into an f32x2 pair -> 6-instr/k matvec.
// ---------------------------------------------------------------------------
__global__ void __launch_bounds__(THREADS, 1)
recurrent_kernel(const float* __restrict__ Whid,
                 const float* __restrict__ noise,
                 float* __restrict__ out, int has_tail)
{
    extern __shared__ float sm[];
    const uint32_t sbase = s2u(sm);

    const int tid   = threadIdx.x;
    const int g     = blockIdx.x >> 3;
    const int rank  = blockIdx.x & 7;
    const int n0r   = rank * 64;
    const int bbase = g * 8;

    // ---- load W slice transposed: Ws[k*64+n] = Whid[n0r+n][k] ----
    for (int i = tid; i < 64 * 128; i += THREADS) {
        int n = i >> 7, kq4 = i & 127;
        float4 v = reinterpret_cast<const float4*>(Whid)[(n0r + n) * 128 + kq4];
        sm[(4 * kq4 + 0) * 64 + n] = v.x;
        sm[(4 * kq4 + 1) * 64 + n] = v.y;
        sm[(4 * kq4 + 2) * 64 + n] = v.z;
        sm[(4 * kq4 + 3) * 64 + n] = v.w;
    }
    __syncthreads();

    // ---- engine / thread mapping ----
    const int e    = tid >> 8;           // engine 0/1
    const int etid = tid & 255;
    // matvec: kq (8 x 64k == source rank) x bg (2 x 2b) x ng (16 x 4n)
    const int kq = etid >> 5;
    const int ng = etid & 15;
    const int bg = (etid >> 4) & 1;
    const uint32_t wp0 = sbase + (uint32_t)(kq * 16384 + ng * 16);
    // reduce/epilogue: one output (b, col) per thread
    const int rb   = etid >> 6;          // 0..3
    const int rn   = etid & 63;
    const int col  = n0r + rn;
    const int gb   = bbase + e * 4 + rb;
    const uint32_t scr_st = sbase + SCR_OFF + (uint32_t)((e * 2048 + kq * 256 + 2 * bg * 64 + 4 * ng) * 4);
    const uint32_t scr_rd = sbase + SCR_OFF + (uint32_t)((e * 2048 + rb * 64 + rn) * 4);
    // staging: chunk (e,kq) layout [k 64][bg 2][b 2] dup'd ull (2KB)
    const int lane = tid & 31;
    const int b_l  = lane >> 3;          // 0..3
    const int kk_l = (lane & 7) * 8;     // 0..56
    const uint32_t hs_ch = sbase + (uint32_t)(HS_OFF + e * 16384 + kq * 2048);
    const uint32_t hs_st = hs_ch + (uint32_t)(kk_l * 32 + (b_l >> 1) * 16 + (b_l & 1) * 8);
    const uint32_t hp0   = hs_ch + (uint32_t)(bg * 16);
    // flags
    unsigned* flagw = &g_flags[g][e][kq * 32];     // this warp waits on src = kq
    unsigned* flagp = &g_flags[g][e][rank * 32];   // this CTA publishes

    // ---- anti-phase seed: engine 1 starts ~1.5k cycles late ----
    if (e == 1) {
        float z = (float)tid;
        #pragma unroll 1
        for (int i = 0; i < 384; i++)
            asm volatile("fma.rn.f32 %0, %0, %1, %2;"
                         : "+f"(z) : "f"(0.9999f), "f"(1e-7f));
        if (z == 1.2345e11f) sm[0] = z;   // never true; keeps the chain live
    }

    float rh = 0.0f;
    // one-step-ahead prefetch registers (s = 0)
    float xc  = out[(size_t)gb * HIDDEN + col];
    float nzc = __ldg(&noise[col]);

    for (int s = 0; s < SEQ; s++) {
        const int par = s & 1;

        // ---- per-warp chunk wait (monotonic flag) ----
        if (s > 0) {
            unsigned f;
            do {
                asm volatile("ld.acquire.gpu.global.u32 %0, [%1];"
                             : "=r"(f) : "l"(flagw) : "memory");
            } while (f < (unsigned)s);
        }

        // ---- stage this warp's chunk: g_h[par] -> smem, DUPLICATED ----
        {
            const float* hsrc = &g_h[par][(size_t)(bbase + e * 4 + b_l) * HIDDEN
                                          + kq * 64 + kk_l];
            float4 v0 = *reinterpret_cast<const float4*>(hsrc);
            float4 v1 = *reinterpret_cast<const float4*>(hsrc + 4);
            asm volatile("st.shared.u64 [%0],      %1;" :: "r"(hs_st), "l"(pk(v0.x, v0.x)));
            asm volatile("st.shared.u64 [%0+32],   %1;" :: "r"(hs_st), "l"(pk(v0.y, v0.y)));
            asm volatile("st.shared.u64 [%0+64],   %1;" :: "r"(hs_st), "l"(pk(v0.z, v0.z)));
            asm volatile("st.shared.u64 [%0+96],   %1;" :: "r"(hs_st), "l"(pk(v0.w, v0.w)));
            asm volatile("st.shared.u64 [%0+128],  %1;" :: "r"(hs_st), "l"(pk(v1.x, v1.x)));
            asm volatile("st.shared.u64 [%0+160],  %1;" :: "r"(hs_st), "l"(pk(v1.y, v1.y)));
            asm volatile("st.shared.u64 [%0+192],  %1;" :: "r"(hs_st), "l"(pk(v1.z, v1.z)));
            asm volatile("st.shared.u64 [%0+224],  %1;" :: "r"(hs_st), "l"(pk(v1.w, v1.w)));
        }
        __syncwarp();

        // ---- prefetch NEXT step's proj + noise (off critical path) ----
        float xn = 0.0f, nzn = 0.0f;
        if (s + 1 < SEQ) {
            xn  = out[((size_t)(s + 1) * BATCH + gb) * HIDDEN + col];
            nzn = __ldg(&noise[(size_t)(s + 1) * HIDDEN + col]);
        }

        // ---- matvec over this warp's 64-k chunk: 6 instr / k ----
        ull a00 = 0, a01 = 0, a10 = 0, a11 = 0;
        #pragma unroll 8
        for (int k = 0; k < 64; k++) {
            ull w01, w23, h0, h1;
            asm("ld.shared.v2.u64 {%0,%1}, [%2];"
                : "=l"(w01), "=l"(w23) : "r"(wp0 + (uint32_t)(k * 256)));
            asm("ld.shared.v2.u64 {%0,%1}, [%2];"
                : "=l"(h0), "=l"(h1) : "r"(hp0 + (uint32_t)(k * 32)));
            fma2(a00, h0, w01); fma2(a01, h0, w23);
            fma2(a10, h1, w01); fma2(a11, h1, w23);
        }
        asm volatile("st.shared.v2.u64 [%0],     {%1,%2};" :: "r"(scr_st), "l"(a00), "l"(a01));
        asm volatile("st.shared.v2.u64 [%0+256], {%1,%2};" :: "r"(scr_st), "l"(a10), "l"(a11));

        // engine barrier #1: matvec partials visible
        asm volatile("bar.sync %0, 256;" :: "r"(1 + e) : "memory");

        // ---- reduce 8 k-partials + state update ----
        float acc = 0.0f;
        #pragma unroll
        for (int q = 0; q < 8; q++) {
            float v;
            asm("ld.shared.f32 %0, [%1];" : "=f"(v) : "r"(scr_rd + (uint32_t)(q * 1024)));
            acc += v;
        }
        float hn = 0.5f * rh + 0.5f * (acc + xc + nzc);
        rh = hn;

        if (s < SEQ - 1) {
            // publish FIRST (critical path), then flag, then the d_out store
            g_h[par ^ 1][(size_t)gb * HIDDEN + col] = fmaxf(hn, 0.0f);

            // engine barrier #2: all publishes done; protects scr/HS WAR
            asm volatile("bar.sync %0, 256;" :: "r"(1 + e) : "memory");

            if (etid == 0) {
                __threadfence();
                unsigned nf = (unsigned)(s + 1);
                asm volatile("st.relaxed.gpu.global.u32 [%0], %1;"
                             :: "l"(flagp), "r"(nf) : "memory");
            }
        }
        // d_out store AFTER the flag: off the inter-CTA critical path
        out[((size_t)s * BATCH + gb) * HIDDEN + col] = hn;
        xc = xn; nzc = nzn;
    }

    // ---- fused tail: final hidden state ----
    if (has_tail)
        out[(size_t)SEQ * BATCH * HIDDEN + (size_t)gb * HIDDEN + col] = rh;
}

// ---------------------------------------------------------------------------
extern "C" void kernel_launch(void* const* d_in, const int* in_sizes, int n_in,
                              void* d_out, int out_size)
{
    const float* input = (const float*)d_in[0];
    const float* W_in  = (const float*)d_in[1];
    const float* W_hid = (const float*)d_in[2];
    const float* noise = (const float*)d_in[3];
    float* out = (float*)d_out;

    cudaFuncSetAttribute(recurrent_kernel,
                         cudaFuncAttributeMaxDynamicSharedMemorySize, SMEM_BYTES);

    init_kernel<<<288, 256>>>();

    dim3 grid((SEQ * BATCH) / 64, HIDDEN / 64);
    proj_kernel<<<grid, 256>>>(input, W_in, out);

    int has_tail = (out_size >= SEQ * BATCH * HIDDEN + BATCH * HIDDEN) ? 1 : 0;
    recurrent_kernel<<<128, THREADS, SMEM_BYTES>>>(W_hid, noise, out, has_tail);
}

// round 15
// speedup vs baseline: 1.2602x; 1.2602x over previous
#include <cuda_runtime.h>
#include <cstdint>

typedef unsigned long long ull;

#define SEQ    512
#define BATCH  128
#define INPUT  128
#define HIDDEN 512
#define THREADS 512

// ---- recurrent smem layout (bytes) ----
// W slice  [512 k][64 n] fp32                          131072
// HS dup-staged h: [kq 16][k 32][b 8] ull (2KB/warp)    32768
// scr partials: [kq 16][b 8][n 64] fp32                 32768
#define HS_OFF   131072
#define SCR_OFF  163840
#define SMEM_BYTES 196608

// ---- global exchange state (no allocations allowed) ----
__device__ float    g_h[2][BATCH * HIDDEN];        // relu(h), parity buffered
__device__ unsigned g_flags[16][8 * 32];           // [group][src*32] 128B-spaced

// ---------------------------------------------------------------------------
// init: zero g_h[0] (h0 = 0) and all flags (every launch -> deterministic)
// ---------------------------------------------------------------------------
__global__ void init_kernel()
{
    int i = blockIdx.x * blockDim.x + threadIdx.x;
    if (i < BATCH * HIDDEN) g_h[0][i] = 0.0f;
    if (i < 16 * 8 * 32) ((unsigned*)g_flags)[i] = 0u;
}

// ---------------------------------------------------------------------------
// Phase 1: proj[row,n] = sum_k input[row,k] * W_in[n,k] -> d_out
// ---------------------------------------------------------------------------
__global__ __launch_bounds__(256) void proj_kernel(
    const float* __restrict__ A, const float* __restrict__ W,
    float* __restrict__ C)
{
    __shared__ float As[64][65];
    __shared__ float Bs[64][65];
    const int tid = threadIdx.x, tx = tid & 15, ty = tid >> 4;
    const int row0 = blockIdx.x * 64, n0 = blockIdx.y * 64;
    float acc[4][4] = {};
    for (int k0 = 0; k0 < INPUT; k0 += 64) {
        #pragma unroll
        for (int i = 0; i < 16; i++) {
            int e = tid + i * 256, r = e >> 6, kk = e & 63;
            As[kk][r] = A[(row0 + r) * INPUT + k0 + kk];
            Bs[kk][r] = W[(n0 + r) * INPUT + k0 + kk];
        }
        __syncthreads();
        #pragma unroll 8
        for (int k = 0; k < 64; k++) {
            float a[4], b[4];
            #pragma unroll
            for (int i = 0; i < 4; i++) a[i] = As[k][ty * 4 + i];
            #pragma unroll
            for (int j = 0; j < 4; j++) b[j] = Bs[k][tx * 4 + j];
            #pragma unroll
            for (int i = 0; i < 4; i++)
                #pragma unroll
                for (int j = 0; j < 4; j++) acc[i][j] += a[i] * b[j];
        }
        __syncthreads();
    }
    #pragma unroll
    for (int i = 0; i < 4; i++) {
        int row = row0 + ty * 4 + i;
        #pragma unroll
        for (int j = 0; j < 4; j++)
            C[row * HIDDEN + n0 + tx * 4 + j] = acc[i][j];
    }
}

// ---- helpers ---------------------------------------------------------------
__device__ __forceinline__ void fma2(ull& d, ull a, ull b) {
    asm("fma.rn.f32x2 %0, %1, %2, %0;" : "+l"(d) : "l"(a), "l"(b));
}
__device__ __forceinline__ ull pk(float lo, float hi) {
    ull d; asm("mov.b64 %0, {%1, %2};" : "=l"(d) : "f"(lo), "f"(hi)); return d;
}
__device__ __forceinline__ uint32_t s2u(const void* p) {
    uint32_t a;
    asm("{ .reg .u64 t; cvta.to.shared.u64 t, %1; cvt.u32.u64 %0, t; }" : "=r"(a) : "l"(p));
    return a;
}

// ---------------------------------------------------------------------------
// Phase 2: persistent recurrence, SINGLE 512-thread engine per CTA (W read
//   once per step). 128 CTAs: group g = blockIdx/8 owns batch rows [8g,8g+8);
//   rank = blockIdx%8 owns hidden cols [64r,64r+64).
//   Exchange via L2 + per-source monotonic flags (R13-validated fabric).
//   Warp kq consumes k in [32kq, 32kq+32) -> waits only on src = kq>>1.
//   Matvec: thread tile 4b(dup f32x2) x 4n x 32k, 12 instr / 8 FFMA2 per k.
// ---------------------------------------------------------------------------
__global__ void __launch_bounds__(THREADS, 1)
recurrent_kernel(const float* __restrict__ Whid,
                 const float* __restrict__ noise,
                 float* __restrict__ out, int has_tail)
{
    extern __shared__ float sm[];
    const uint32_t sbase = s2u(sm);

    const int tid   = threadIdx.x;
    const int g     = blockIdx.x >> 3;
    const int rank  = blockIdx.x & 7;
    const int n0r   = rank * 64;
    const int bbase = g * 8;

    // ---- load W slice transposed: Ws[k*64+n] = Whid[n0r+n][k] ----
    for (int i = tid; i < 64 * 128; i += THREADS) {
        int n = i >> 7, kq4 = i & 127;
        float4 v = reinterpret_cast<const float4*>(Whid)[(n0r + n) * 128 + kq4];
        sm[(4 * kq4 + 0) * 64 + n] = v.x;
        sm[(4 * kq4 + 1) * 64 + n] = v.y;
        sm[(4 * kq4 + 2) * 64 + n] = v.z;
        sm[(4 * kq4 + 3) * 64 + n] = v.w;
    }
    __syncthreads();

    // ---- thread mapping ----
    const int kq   = tid >> 5;            // warp = k-slice [32kq, 32kq+32)
    const int lane = tid & 31;
    const int ng   = lane & 15;           // n = 4*ng
    const int bg   = lane >> 4;           // b in {4bg .. 4bg+3}
    const uint32_t wp0 = sbase + (uint32_t)(kq * 8192 + ng * 16);
    const uint32_t hs_ch = sbase + (uint32_t)(HS_OFF + kq * 2048);   // warp chunk
    const uint32_t hp0   = hs_ch + (uint32_t)(bg * 32);
    // staging: lane -> (b_l, kk_l)
    const int b_l  = lane >> 2;           // 0..7
    const int kk_l = (lane & 3) * 8;      // 0,8,16,24
    const uint32_t hs_st = hs_ch + (uint32_t)(kk_l * 64 + b_l * 8);
    // scr: [kq][b 8][n 64]
    const uint32_t scr_st = sbase + (uint32_t)(SCR_OFF + kq * 2048 + bg * 1024 + ng * 16);
    // reduce/epilogue: one output (b, col) per thread
    const int rb  = tid >> 6;             // 0..7
    const int rn  = tid & 63;
    const int col = n0r + rn;
    const int gb  = bbase + rb;
    const uint32_t scr_rd = sbase + (uint32_t)(SCR_OFF + rb * 256 + rn * 4);
    // flags
    unsigned* flagw = &g_flags[g][(kq >> 1) * 32];   // warp waits on src = kq>>1
    unsigned* flagp = &g_flags[g][rank * 32];        // this CTA publishes

    float rh = 0.0f;

    for (int s = 0; s < SEQ; s++) {
        const int par = s & 1;

        // ---- per-warp chunk wait (monotonic flag) ----
        if (s > 0) {
            unsigned f;
            do {
                asm volatile("ld.acquire.gpu.global.u32 %0, [%1];"
                             : "=r"(f) : "l"(flagw) : "memory");
            } while (f < (unsigned)s);
        }

        // ---- stage this warp's chunk: g_h[par] -> smem, DUPLICATED pairs ----
        {
            const float* hsrc = &g_h[par][(size_t)(bbase + b_l) * HIDDEN
                                          + kq * 32 + kk_l];
            float x0, x1, x2, x3, y0, y1, y2, y3;
            asm volatile("ld.relaxed.gpu.global.v4.f32 {%0,%1,%2,%3}, [%4];"
                         : "=f"(x0), "=f"(x1), "=f"(x2), "=f"(x3) : "l"(hsrc));
            asm volatile("ld.relaxed.gpu.global.v4.f32 {%0,%1,%2,%3}, [%4];"
                         : "=f"(y0), "=f"(y1), "=f"(y2), "=f"(y3) : "l"(hsrc + 4));
            // HS[kq][klocal][b]: 8 consecutive k rows, this lane's b slot
            asm volatile("st.shared.u64 [%0],      %1;" :: "r"(hs_st), "l"(pk(x0, x0)));
            asm volatile("st.shared.u64 [%0+64],   %1;" :: "r"(hs_st), "l"(pk(x1, x1)));
            asm volatile("st.shared.u64 [%0+128],  %1;" :: "r"(hs_st), "l"(pk(x2, x2)));
            asm volatile("st.shared.u64 [%0+192],  %1;" :: "r"(hs_st), "l"(pk(x3, x3)));
            asm volatile("st.shared.u64 [%0+256],  %1;" :: "r"(hs_st), "l"(pk(y0, y0)));
            asm volatile("st.shared.u64 [%0+320],  %1;" :: "r"(hs_st), "l"(pk(y1, y1)));
            asm volatile("st.shared.u64 [%0+384],  %1;" :: "r"(hs_st), "l"(pk(y2, y2)));
            asm volatile("st.shared.u64 [%0+448],  %1;" :: "r"(hs_st), "l"(pk(y3, y3)));
        }
        __syncwarp();

        // proj (in d_out) + noise for the epilogue (latency hidden by matvec)
        float* optr = out + ((size_t)s * BATCH + gb) * HIDDEN + col;
        float x  = *optr;
        float nz = __ldg(&noise[(size_t)s * HIDDEN + col]);

        // ---- matvec over this warp's 32-k slice: 4b x 4n per thread ----
        ull a0 = 0, a1 = 0, a2 = 0, a3 = 0;   // (b+0, np0/1), (b+1, np0/1)
        ull a4 = 0, a5 = 0, a6 = 0, a7 = 0;   // (b+2, ...),  (b+3, ...)
        #pragma unroll 8
        for (int k = 0; k < 32; k++) {
            ull w01, w23, hd0, hd1, hd2, hd3;
            asm("ld.shared.v2.u64 {%0,%1}, [%2];"
                : "=l"(w01), "=l"(w23) : "r"(wp0 + (uint32_t)(k * 256)));
            asm("ld.shared.v2.u64 {%0,%1}, [%2];"
                : "=l"(hd0), "=l"(hd1) : "r"(hp0 + (uint32_t)(k * 64)));
            asm("ld.shared.v2.u64 {%0,%1}, [%2];"
                : "=l"(hd2), "=l"(hd3) : "r"(hp0 + (uint32_t)(k * 64 + 16)));
            fma2(a0, hd0, w01); fma2(a1, hd0, w23);
            fma2(a2, hd1, w01); fma2(a3, hd1, w23);
            fma2(a4, hd2, w01); fma2(a5, hd2, w23);
            fma2(a6, hd3, w01); fma2(a7, hd3, w23);
        }
        // scr[kq][4bg+bi][n]: n-pairs contiguous
        asm volatile("st.shared.u64 [%0+0],   %1;" :: "r"(scr_st), "l"(a0));
        asm volatile("st.shared.u64 [%0+8],   %1;" :: "r"(scr_st), "l"(a1));
        asm volatile("st.shared.u64 [%0+256], %1;" :: "r"(scr_st), "l"(a2));
        asm volatile("st.shared.u64 [%0+264], %1;" :: "r"(scr_st), "l"(a3));
        asm volatile("st.shared.u64 [%0+512], %1;" :: "r"(scr_st), "l"(a4));
        asm volatile("st.shared.u64 [%0+520], %1;" :: "r"(scr_st), "l"(a5));
        asm volatile("st.shared.u64 [%0+768], %1;" :: "r"(scr_st), "l"(a6));
        asm volatile("st.shared.u64 [%0+776], %1;" :: "r"(scr_st), "l"(a7));

        __syncthreads();   // matvec partials visible

        // ---- reduce 16 k-partials + state update ----
        float acc = 0.0f;
        #pragma unroll
        for (int q = 0; q < 16; q++) {
            float v;
            asm("ld.shared.f32 %0, [%1];" : "=f"(v) : "r"(scr_rd + (uint32_t)(q * 2048)));
            acc += v;
        }
        float hn = 0.5f * rh + 0.5f * (acc + x + nz);
        rh = hn;

        if (s < SEQ - 1) {
            // publish relu(h_new) FIRST (inter-CTA critical path)
            g_h[par ^ 1][(size_t)gb * HIDDEN + col] = fmaxf(hn, 0.0f);

            __syncthreads();   // all publishes issued; protects scr/HS WAR

            if (tid == 0) {
                __threadfence();
                unsigned nf = (unsigned)(s + 1);
                asm volatile("st.relaxed.gpu.global.u32 [%0], %1;"
                             :: "l"(flagp), "r"(nf) : "memory");
            }
        } else {
            __syncthreads();
        }
        // d_out store AFTER the flag: off the inter-CTA critical path
        *optr = hn;
    }

    // ---- fused tail: final hidden state ----
    if (has_tail)
        out[(size_t)SEQ * BATCH * HIDDEN + (size_t)gb * HIDDEN + col] = rh;
}

// ---------------------------------------------------------------------------
extern "C" void kernel_launch(void* const* d_in, const int* in_sizes, int n_in,
                              void* d_out, int out_size)
{
    const float* input = (const float*)d_in[0];
    const float* W_in  = (const float*)d_in[1];
    const float* W_hid = (const float*)d_in[2];
    const float* noise = (const float*)d_in[3];
    float* out = (float*)d_out;

    cudaFuncSetAttribute(recurrent_kernel,
                         cudaFuncAttributeMaxDynamicSharedMemorySize, SMEM_BYTES);

    init_kernel<<<288, 256>>>();

    dim3 grid((SEQ * BATCH) / 64, HIDDEN / 64);
    proj_kernel<<<grid, 256>>>(input, W_in, out);

    int has_tail = (out_size >= SEQ * BATCH * HIDDEN + BATCH * HIDDEN) ? 1 : 0;
    recurrent_kernel<<<128, THREADS, SMEM_BYTES>>>(W_hid, noise, out, has_tail);
}